// round 4
// baseline (speedup 1.0000x reference)
#include <cuda_runtime.h>
#include <math.h>

#define B_DIM 256
#define V_DIM 50257
#define SEGS  4
#define SEG_LEN 12565                 // ceil(V/4)
#define N4_AVG ((B_DIM * V_DIM) / 4)

// Partial sum-of-exp per row segment: [b*SEGS + seg]
__device__ float g_partial[SEGS * B_DIM];

// ---------------------------------------------------------------------------
// Kernel 1: zero avg region + branch-free partial sum-of-exp (4 CTAs/row).
// ---------------------------------------------------------------------------
__global__ __launch_bounds__(256)
void stats_and_zero(const float* __restrict__ w, float4* __restrict__ avg4) {
    const int bid = blockIdx.x;

    {   // zero share of avg
        const float4 z = make_float4(0.f, 0.f, 0.f, 0.f);
        const int stride = gridDim.x * blockDim.x;
        for (int i = bid * blockDim.x + threadIdx.x; i < N4_AVG; i += stride)
            avg4[i] = z;
    }

    const int b   = bid >> 2;
    const int seg = bid & 3;
    const int vs  = seg * SEG_LEN;
    const int ve  = (vs + SEG_LEN < V_DIM) ? (vs + SEG_LEN) : V_DIM;
    const float* row = w + (size_t)b * V_DIM;

    float s0 = 0.f, s1 = 0.f, s2 = 0.f, s3 = 0.f;
    int v = vs + threadIdx.x;
    for (; v + 768 < ve; v += 1024) {
        const float x0 = __ldg(row + v);
        const float x1 = __ldg(row + v + 256);
        const float x2 = __ldg(row + v + 512);
        const float x3 = __ldg(row + v + 768);
        s0 += __expf(x0); s1 += __expf(x1);
        s2 += __expf(x2); s3 += __expf(x3);
    }
    for (; v < ve; v += 256) s0 += __expf(__ldg(row + v));

    float s = (s0 + s1) + (s2 + s3);
    #pragma unroll
    for (int o = 16; o > 0; o >>= 1)
        s += __shfl_xor_sync(0xFFFFFFFFu, s, o);

    __shared__ float ss[8];
    const int lane = threadIdx.x & 31;
    const int wid  = threadIdx.x >> 5;
    if (lane == 0) ss[wid] = s;
    __syncthreads();
    if (wid == 0) {
        s = (lane < 8) ? ss[lane] : 0.0f;
        #pragma unroll
        for (int o = 4; o > 0; o >>= 1)
            s += __shfl_xor_sync(0xFFFFFFFFu, s, o);
        if (lane == 0) g_partial[bid] = s;
    }
}

__device__ __forceinline__ float row_inv(int b) {
    return 1.0f / (__ldg(&g_partial[4 * b + 0]) + __ldg(&g_partial[4 * b + 1]) +
                   __ldg(&g_partial[4 * b + 2]) + __ldg(&g_partial[4 * b + 3]));
}

// ---------------------------------------------------------------------------
// Kernel 2a: PURE scatter. No smem, no barriers. 8 items/thread,
// warp-coalesced loads batched up front, then 8 no-return atomics (REDG).
// Streaming reads use __ldcs to protect avg's L2 residency.
// grid = (25, 256): blockIdx.x covers 2048 items of row blockIdx.y.
// Blocks 0..23 are full (49152 <= 50257); block 24 is predicated.
// ---------------------------------------------------------------------------
__global__ __launch_bounds__(256)
void scatter_only(const int*   __restrict__ idx,
                  const float* __restrict__ w,
                  float*       __restrict__ avg) {
    const int b = blockIdx.y;
    const size_t rowoff = (size_t)b * V_DIM;
    const float inv = row_inv(b);

    const int base = blockIdx.x * 2048 + threadIdx.x;

    if (blockIdx.x < 24) {          // fast path: all 8 valid
        float x[8]; int id[8];
        #pragma unroll
        for (int k = 0; k < 8; k++) x[k]  = __ldcs(w   + rowoff + base + k * 256);
        #pragma unroll
        for (int k = 0; k < 8; k++) id[k] = __ldcs(idx + rowoff + base + k * 256);
        #pragma unroll
        for (int k = 0; k < 8; k++)
            atomicAdd(&avg[rowoff + id[k]], __expf(x[k]) * inv);
    } else {                        // tail block
        #pragma unroll
        for (int k = 0; k < 8; k++) {
            const int v = base + k * 256;
            if (v < V_DIM) {
                const float e = __expf(__ldcs(w + rowoff + v)) * inv;
                atomicAdd(&avg[rowoff + __ldcs(idx + rowoff + v)], e);
            }
        }
    }
}

// ---------------------------------------------------------------------------
// Kernel 2b: PURE transpose. Recompute weights from w, write wT coalesced.
// 32b x 128v tiles, XOR-swizzled float4 smem tile (both phases conflict-free).
// ---------------------------------------------------------------------------
__global__ __launch_bounds__(1024)
void transpose_only(const float* __restrict__ w,
                    float*       __restrict__ wT) {
    __shared__ float4 tile[32][32];

    const int vt = blockIdx.x;
    const int bt = blockIdx.y;
    const int tx = threadIdx.x;
    const int ty = threadIdx.y;

    const int b = bt * 32 + ty;
    const size_t rowoff = (size_t)b * V_DIM;
    const float inv = row_inv(b);

    const int vbase = vt * 128 + tx * 4;
    float4 wv;
    if (vbase + 3 < V_DIM) {
        float x[4];
        #pragma unroll
        for (int k = 0; k < 4; k++) x[k] = __ldcs(w + rowoff + vbase + k);
        #pragma unroll
        for (int k = 0; k < 4; k++) ((float*)&wv)[k] = __expf(x[k]) * inv;
    } else {
        #pragma unroll
        for (int k = 0; k < 4; k++) {
            const int v = vbase + k;
            ((float*)&wv)[k] = (v < V_DIM) ? __expf(__ldcs(w + rowoff + v)) * inv : 0.0f;
        }
    }
    tile[ty][tx ^ (ty >> 2)] = wv;
    __syncthreads();

    const int t = ty * 32 + tx;
    const int r = t >> 3;
    const int c = t & 7;
    const int v = vt * 128 + r;
    if (v < V_DIM) {
        const int wq  = r >> 2;
        const int sub = r & 3;
        float4 o;
        #pragma unroll
        for (int j = 0; j < 4; j++)
            ((float*)&o)[j] = ((const float*)&tile[c * 4 + j][wq ^ c])[sub];
        __stcs((float4*)&wT[(size_t)v * B_DIM + bt * 32 + c * 4], o);
    }
}

// ---------------------------------------------------------------------------
extern "C" void kernel_launch(void* const* d_in, const int* in_sizes, int n_in,
                              void* d_out, int out_size) {
    const int*   indices = (const int*)d_in[0];
    const float* w_es    = (const float*)d_in[1];

    float* avg = (float*)d_out;                           // [B, V]
    float* wT  = (float*)d_out + (size_t)B_DIM * V_DIM;   // [V, B]

    stats_and_zero<<<SEGS * B_DIM, 256>>>(w_es, (float4*)avg);

    dim3 sgrid((V_DIM + 2047) / 2048, B_DIM);             // 25 x 256
    scatter_only<<<sgrid, 256>>>(indices, w_es, avg);

    dim3 tgrid((V_DIM + 127) / 128, B_DIM / 32);          // 393 x 8
    dim3 tblock(32, 32);
    transpose_only<<<tgrid, tblock>>>(w_es, wT);
}

// round 5
// speedup vs baseline: 1.1074x; 1.1074x over previous
#include <cuda_runtime.h>
#include <math.h>

#define B_DIM 256
#define V_DIM 50257
#define SEGS  4
#define SEG_LEN 12565                 // ceil(V/4)
#define N4_AVG ((B_DIM * V_DIM) / 4)

// Partial sum-of-exp per row segment: [b*SEGS + seg]
__device__ float g_partial[SEGS * B_DIM];

// ---------------------------------------------------------------------------
// Kernel 1: zero avg region + float4-vectorized partial sum-of-exp.
// 4 CTAs per row (1024 CTAs x 256 thr). Row-segment start has alignment
// phase (b+seg)&3 (V = 50257 ≡ 1 mod 4, SEG_LEN ≡ 1 mod 4): peel scalar
// head/tail, float4 body unrolled x2 with independent accumulators.
// ---------------------------------------------------------------------------
__global__ __launch_bounds__(256)
void stats_and_zero(const float* __restrict__ w, float4* __restrict__ avg4) {
    const int bid = blockIdx.x;

    {   // zero share of avg (grid-stride float4)
        const float4 z = make_float4(0.f, 0.f, 0.f, 0.f);
        const int stride = gridDim.x * blockDim.x;
        for (int i = bid * blockDim.x + threadIdx.x; i < N4_AVG; i += stride)
            avg4[i] = z;
    }

    const int b   = bid >> 2;
    const int seg = bid & 3;
    const int vs  = seg * SEG_LEN;
    const int ve  = (vs + SEG_LEN < V_DIM) ? (vs + SEG_LEN) : V_DIM;
    const size_t rowoff = (size_t)b * V_DIM;

    const int p    = (b + seg) & 3;          // alignment phase of element vs
    const int head = (4 - p) & 3;
    const int va   = vs + head;              // first float4-aligned element
    const int n4   = (ve - va) >> 2;         // full float4s in body
    const int vtail = va + (n4 << 2);        // first tail element

    float s0 = 0.f, s1 = 0.f, s2 = 0.f, s3 = 0.f;

    // scalar head (0..3 elements)
    if (threadIdx.x < head)
        s0 += __expf(__ldg(w + rowoff + vs + threadIdx.x));

    // vector body, unrolled x2
    const float4* w4 = (const float4*)(w + rowoff + va);
    int i = threadIdx.x;
    for (; i + 256 < n4; i += 512) {
        const float4 a = __ldg(w4 + i);
        const float4 c = __ldg(w4 + i + 256);
        s0 += __expf(a.x); s1 += __expf(a.y);
        s2 += __expf(a.z); s3 += __expf(a.w);
        s0 += __expf(c.x); s1 += __expf(c.y);
        s2 += __expf(c.z); s3 += __expf(c.w);
    }
    if (i < n4) {
        const float4 a = __ldg(w4 + i);
        s0 += __expf(a.x); s1 += __expf(a.y);
        s2 += __expf(a.z); s3 += __expf(a.w);
    }

    // scalar tail (0..3 elements)
    for (int v = vtail + threadIdx.x; v < ve; v += 256)
        s0 += __expf(__ldg(w + rowoff + v));

    float s = (s0 + s1) + (s2 + s3);
    #pragma unroll
    for (int o = 16; o > 0; o >>= 1)
        s += __shfl_xor_sync(0xFFFFFFFFu, s, o);

    __shared__ float ss[8];
    const int lane = threadIdx.x & 31;
    const int wid  = threadIdx.x >> 5;
    if (lane == 0) ss[wid] = s;
    __syncthreads();
    if (wid == 0) {
        s = (lane < 8) ? ss[lane] : 0.0f;
        #pragma unroll
        for (int o = 4; o > 0; o >>= 1)
            s += __shfl_xor_sync(0xFFFFFFFFu, s, o);
        if (lane == 0) g_partial[bid] = s;
    }
}

// ---------------------------------------------------------------------------
// Kernel 2 (R3 fused version, measured 81.2us): weights + scatter-add +
// transposed write. 32b x 128v tiles, block (32,32), 4 v-elems/thread.
// Transpose traffic hides under the L2-atomic wall.
// ---------------------------------------------------------------------------
__global__ __launch_bounds__(1024)
void weights_scatter_transpose(const int*   __restrict__ idx,
                               const float* __restrict__ w,
                               float*       __restrict__ avg,
                               float*       __restrict__ wT) {
    __shared__ float4 tile[32][32];

    const int vt = blockIdx.x;
    const int bt = blockIdx.y;
    const int tx = threadIdx.x;
    const int ty = threadIdx.y;

    const int b = bt * 32 + ty;
    const size_t rowoff = (size_t)b * V_DIM;
    const float inv = 1.0f / (__ldg(&g_partial[4 * b + 0]) + __ldg(&g_partial[4 * b + 1]) +
                              __ldg(&g_partial[4 * b + 2]) + __ldg(&g_partial[4 * b + 3]));

    const int vbase = vt * 128 + tx * 4;
    const bool full = (vbase + 3) < V_DIM;

    if (full) {
        float x[4]; int id[4];
        #pragma unroll
        for (int k = 0; k < 4; k++) x[k]  = __ldg(w + rowoff + vbase + k);
        #pragma unroll
        for (int k = 0; k < 4; k++) id[k] = __ldcs(idx + rowoff + vbase + k);

        float4 wv;
        #pragma unroll
        for (int k = 0; k < 4; k++) {
            const float e = __expf(x[k]) * inv;
            ((float*)&wv)[k] = e;
            atomicAdd(&avg[rowoff + id[k]], e);     // no-return -> REDG
        }
        tile[ty][tx ^ (ty >> 2)] = wv;
    } else {
        float4 wv;
        #pragma unroll
        for (int k = 0; k < 4; k++) {
            const int v = vbase + k;
            float e = 0.0f;
            if (v < V_DIM) {
                e = __expf(__ldg(w + rowoff + v)) * inv;
                atomicAdd(&avg[rowoff + __ldcs(idx + rowoff + v)], e);
            }
            ((float*)&wv)[k] = e;
        }
        tile[ty][tx ^ (ty >> 2)] = wv;
    }
    __syncthreads();

    const int t = ty * 32 + tx;
    const int r = t >> 3;
    const int c = t & 7;
    const int v = vt * 128 + r;
    if (v < V_DIM) {
        const int wq  = r >> 2;
        const int sub = r & 3;
        float4 o;
        #pragma unroll
        for (int j = 0; j < 4; j++)
            ((float*)&o)[j] = ((const float*)&tile[c * 4 + j][wq ^ c])[sub];
        __stcs((float4*)&wT[(size_t)v * B_DIM + bt * 32 + c * 4], o);
    }
}

// ---------------------------------------------------------------------------
extern "C" void kernel_launch(void* const* d_in, const int* in_sizes, int n_in,
                              void* d_out, int out_size) {
    const int*   indices = (const int*)d_in[0];
    const float* w_es    = (const float*)d_in[1];

    float* avg = (float*)d_out;                           // [B, V]
    float* wT  = (float*)d_out + (size_t)B_DIM * V_DIM;   // [V, B]

    stats_and_zero<<<SEGS * B_DIM, 256>>>(w_es, (float4*)avg);

    dim3 grid((V_DIM + 127) / 128, B_DIM / 32);  // 393 x 8
    dim3 block(32, 32);
    weights_scatter_transpose<<<grid, block>>>(indices, w_es, avg, wT);
}